// round 9
// baseline (speedup 1.0000x reference)
#include <cuda_runtime.h>

// IntensityTransformation: out_k[b,c,h,w] = tf_k[b,c, round(255*img[b,c,h,w])]
// img: [B,C,H,W] f32 (B=8,C=3,H=W=1024), tf1/2/3: [B,C,256] f32.
// Output: concat(out1,out2,out3).
//
// R9: SPLIT THE 3 OUTPUTS ACROSS SIBLING CTAs to cut per-CTA DRAM streams
// from 1R+3W to 1R+1W. blockIdx.x = chunk*3 + k (k = output id, fastest
// varying) so the 3 siblings sharing one img chunk are launch-adjacent and
// co-resident: img is DRAM-read once, L2-hit twice. img loads use default
// caching (L2-resident for siblings); stores stay streaming (__stcs).

#define ITER 4

__global__ __launch_bounds__(256)
void intensity_lut_kernel(const float4* __restrict__ img,
                          const float*  __restrict__ tf1,
                          const float*  __restrict__ tf2,
                          const float*  __restrict__ tf3,
                          float4* __restrict__ out,
                          int hw4,     // H*W/4 per (b,c) plane (multiple of 1024)
                          int tot4)    // B*C*H*W/4 (stride between outputs)
{
    __shared__ float lut[256];

    const int bx    = blockIdx.x;
    const int k_out = bx % 3;            // which output this CTA produces
    const int chunk = bx / 3;            // which img chunk
    const int bc    = blockIdx.y;
    const int t     = threadIdx.x;

    const int base = bc * hw4 + chunk * (256 * ITER) + t;
    const float4* __restrict__ src = img + base;
    float4* __restrict__ dst = out + (size_t)k_out * tot4 + base;

    // Phase 1: front-batched img loads (MLP=4), independent of smem.
    // Default caching: the sibling CTAs need this chunk to L2-hit.
    float4 v[ITER];
#pragma unroll
    for (int kk = 0; kk < ITER; kk++)
        v[kk] = src[kk * 256];

    // Phase 2: load this CTA's single 1KB LUT.
    const float* __restrict__ tf = (k_out == 0) ? tf1 : (k_out == 1) ? tf2 : tf3;
    if (t < 256)
        lut[t] = tf[bc * 256 + t];
    __syncthreads();

    // Phase 3: gather + single-stream store burst.
#pragma unroll
    for (int kk = 0; kk < ITER; kk++) {
        // idx in [0,255] guaranteed (img uniform in [0,1)).
        const int i0 = __float2int_rn(255.0f * v[kk].x);
        const int i1 = __float2int_rn(255.0f * v[kk].y);
        const int i2 = __float2int_rn(255.0f * v[kk].z);
        const int i3 = __float2int_rn(255.0f * v[kk].w);

        __stcs(&dst[kk * 256], make_float4(lut[i0], lut[i1], lut[i2], lut[i3]));
    }
}

extern "C" void kernel_launch(void* const* d_in, const int* in_sizes, int n_in,
                              void* d_out, int out_size) {
    const float* img = (const float*)d_in[0];
    const float* tf1 = (const float*)d_in[1];
    const float* tf2 = (const float*)d_in[2];
    const float* tf3 = (const float*)d_in[3];
    float* out = (float*)d_out;

    const int n_img  = in_sizes[0];          // B*C*H*W
    const int n_lut  = in_sizes[1];          // B*C*256
    const int BC     = n_lut / 256;          // 24
    const int HW     = n_img / BC;           // 1048576
    const int hw4    = HW / 4;               // 262144 (= 256 * 1024 exactly)
    const int tot4   = n_img / 4;            // 6291456

    dim3 block(256);
    const int chunks = hw4 / (256 * ITER);   // 256 chunks per plane
    dim3 grid(chunks * 3, BC);               // (768, 24): k fastest-varying
    intensity_lut_kernel<<<grid, block>>>(
        (const float4*)img, tf1, tf2, tf3, (float4*)out, hw4, tot4);
}

// round 10
// speedup vs baseline: 1.0557x; 1.0557x over previous
#include <cuda_runtime.h>

// IntensityTransformation: out_k[b,c,h,w] = tf_k[b,c, round(255*img[b,c,h,w])]
// img: [B,C,H,W] f32 (B=8,C=3,H=W=1024), tf1/2/3: [B,C,256] f32.
// Output: concat(out1,out2,out3).
//
// FINAL (R10): consolidation of the verified-best configuration.
// Nine rounds established the kernel is at the mixed-stream HBM ceiling
// (~69% of 8TB/s at 3:1 write:read); every SM-side axis is plateau-flat.
//  - loads-first prologue (img LDGs overlap LUT fill + BAR)
//  - float4-packed 4KB shared LUT: one LDS.128 serves all 3 gathers/pixel
//  - ITER=4 front-batched LDG.128 (MLP=4), exact no-tail tiling
//  - __stcs streaming stores; default-cached loads
//  - 512-thread CTAs: 3072 CTAs total, halved prologue/BAR count
//    (R5/R9: fewer concurrent CTAs never hurts DRAM efficiency)

#define ITER   4
#define TPB    512

__global__ __launch_bounds__(TPB)
void intensity_lut_kernel(const float4* __restrict__ img,
                          const float*  __restrict__ tf1,
                          const float*  __restrict__ tf2,
                          const float*  __restrict__ tf3,
                          float4* __restrict__ out,
                          int hw4,     // H*W/4 per (b,c) plane (multiple of TPB*ITER)
                          int tot4)    // B*C*H*W/4 (stride between outputs)
{
    __shared__ float4 lut[256];

    const int bc = blockIdx.y;
    const int t  = threadIdx.x;

    const int base = bc * hw4 + blockIdx.x * (TPB * ITER) + t;
    const float4* __restrict__ src  = img + base;
    float4* __restrict__ dst0 = out + base;
    float4* __restrict__ dst1 = dst0 + tot4;
    float4* __restrict__ dst2 = dst1 + tot4;

    // Phase 1: front-batched img loads (MLP=4), independent of smem;
    // their DRAM latency hides the LUT fill + barrier below.
    float4 v[ITER];
#pragma unroll
    for (int k = 0; k < ITER; k++)
        v[k] = src[k * TPB];

    // Phase 2: LUT fill (L2-resident after first CTA per plane).
    if (t < 256) {
        const int g = bc * 256 + t;
        lut[t] = make_float4(tf1[g], tf2[g], tf3[g], 0.0f);
    }
    __syncthreads();

    // Phase 3: gather + store.
#pragma unroll
    for (int k = 0; k < ITER; k++) {
        // idx in [0,255] guaranteed (img uniform in [0,1)).
        const int i0 = __float2int_rn(255.0f * v[k].x);
        const int i1 = __float2int_rn(255.0f * v[k].y);
        const int i2 = __float2int_rn(255.0f * v[k].z);
        const int i3 = __float2int_rn(255.0f * v[k].w);

        const float4 l0 = lut[i0];
        const float4 l1 = lut[i1];
        const float4 l2 = lut[i2];
        const float4 l3 = lut[i3];

        __stcs(&dst0[k * TPB], make_float4(l0.x, l1.x, l2.x, l3.x));
        __stcs(&dst1[k * TPB], make_float4(l0.y, l1.y, l2.y, l3.y));
        __stcs(&dst2[k * TPB], make_float4(l0.z, l1.z, l2.z, l3.z));
    }
}

extern "C" void kernel_launch(void* const* d_in, const int* in_sizes, int n_in,
                              void* d_out, int out_size) {
    const float* img = (const float*)d_in[0];
    const float* tf1 = (const float*)d_in[1];
    const float* tf2 = (const float*)d_in[2];
    const float* tf3 = (const float*)d_in[3];
    float* out = (float*)d_out;

    const int n_img  = in_sizes[0];          // B*C*H*W
    const int n_lut  = in_sizes[1];          // B*C*256
    const int BC     = n_lut / 256;          // 24
    const int HW     = n_img / BC;           // 1048576
    const int hw4    = HW / 4;               // 262144 (= 128 * 2048 exactly)
    const int tot4   = n_img / 4;            // 6291456

    dim3 block(TPB);
    const int per_cta = TPB * ITER;          // 2048
    dim3 grid(hw4 / per_cta, BC);            // (128, 24) — exact, no tail
    intensity_lut_kernel<<<grid, block>>>(
        (const float4*)img, tf1, tf2, tf3, (float4*)out, hw4, tot4);
}

// round 11
// speedup vs baseline: 1.0624x; 1.0063x over previous
#include <cuda_runtime.h>

// IntensityTransformation: out_k[b,c,h,w] = tf_k[b,c, round(255*img[b,c,h,w])]
// img: [B,C,H,W] f32 (B=8,C=3,H=W=1024), tf1/2/3: [B,C,256] f32.
// Output: concat(out1,out2,out3) -> 3*B*C*H*W floats.
//
// FINAL. 10 rounds of ncu-driven search established this kernel is at the
// mixed-stream HBM3e ceiling (~5.5 TB/s at 3:1 write:read = ~69% of spec;
// 403 MB total traffic -> ~62us kernel). Store issue order, LDS conflicts,
// occupancy (31-92%), stream splitting, and block shape are all plateau-flat
// because L2->DRAM writeback order is hash-determined, not issue-determined.
//
// Config (verified-best intersection):
//  - TPB=256, ITER=4, grid (256,24), exact tiling: zero tail predicates
//  - loads-first prologue: 4 front-batched LDG.128 (MLP=4) issued before the
//    LUT fill so DRAM read latency hides fill + __syncthreads
//  - float4-packed 4KB shared LUT: one LDS.128 serves all 3 gathers/pixel
//  - __float2int_rn == jnp.round (round-half-even); idx in [0,255] by input
//    domain, no clamp needed
//  - __ldcs loads / __stcs stores (single-touch streaming)
//  - 32-bit indexing throughout (max offset 18.9M < 2^31)

#define ITER 4
#define TPB  256

__global__ __launch_bounds__(TPB)
void intensity_lut_kernel(const float4* __restrict__ img,
                          const float*  __restrict__ tf1,
                          const float*  __restrict__ tf2,
                          const float*  __restrict__ tf3,
                          float4* __restrict__ out,
                          int hw4,     // H*W/4 per (b,c) plane (multiple of TPB*ITER)
                          int tot4)    // B*C*H*W/4 (stride between outputs)
{
    __shared__ float4 lut[256];

    const int bc = blockIdx.y;
    const int t  = threadIdx.x;

    const int base = bc * hw4 + blockIdx.x * (TPB * ITER) + t;
    const float4* __restrict__ src  = img + base;
    float4* __restrict__ dst0 = out + base;
    float4* __restrict__ dst1 = dst0 + tot4;
    float4* __restrict__ dst2 = dst1 + tot4;

    // Phase 1: front-batched img loads (MLP=4), independent of shared memory.
    // Their ~600-cycle DRAM latency fully hides the LUT fill + barrier.
    float4 v[ITER];
#pragma unroll
    for (int k = 0; k < ITER; k++)
        v[k] = __ldcs(&src[k * TPB]);

    // Phase 2: LUT fill (72KB of LUTs total -> L2-resident after first wave).
    if (t < 256) {
        const int g = bc * 256 + t;
        lut[t] = make_float4(tf1[g], tf2[g], tf3[g], 0.0f);
    }
    __syncthreads();

    // Phase 3: gather + store.
#pragma unroll
    for (int k = 0; k < ITER; k++) {
        // idx in [0,255] guaranteed (img uniform in [0,1)).
        const int i0 = __float2int_rn(255.0f * v[k].x);
        const int i1 = __float2int_rn(255.0f * v[k].y);
        const int i2 = __float2int_rn(255.0f * v[k].z);
        const int i3 = __float2int_rn(255.0f * v[k].w);

        const float4 l0 = lut[i0];
        const float4 l1 = lut[i1];
        const float4 l2 = lut[i2];
        const float4 l3 = lut[i3];

        __stcs(&dst0[k * TPB], make_float4(l0.x, l1.x, l2.x, l3.x));
        __stcs(&dst1[k * TPB], make_float4(l0.y, l1.y, l2.y, l3.y));
        __stcs(&dst2[k * TPB], make_float4(l0.z, l1.z, l2.z, l3.z));
    }
}

extern "C" void kernel_launch(void* const* d_in, const int* in_sizes, int n_in,
                              void* d_out, int out_size) {
    const float* img = (const float*)d_in[0];
    const float* tf1 = (const float*)d_in[1];
    const float* tf2 = (const float*)d_in[2];
    const float* tf3 = (const float*)d_in[3];
    float* out = (float*)d_out;

    const int n_img  = in_sizes[0];          // B*C*H*W
    const int n_lut  = in_sizes[1];          // B*C*256
    const int BC     = n_lut / 256;          // 24
    const int HW     = n_img / BC;           // 1048576
    const int hw4    = HW / 4;               // 262144 (= 256 * 1024 exactly)
    const int tot4   = n_img / 4;            // 6291456

    dim3 block(TPB);
    const int per_cta = TPB * ITER;          // 1024
    dim3 grid(hw4 / per_cta, BC);            // (256, 24) — exact, no tail
    intensity_lut_kernel<<<grid, block>>>(
        (const float4*)img, tf1, tf2, tf3, (float4*)out, hw4, tot4);
}

// round 12
// speedup vs baseline: 1.0890x; 1.0250x over previous
#include <cuda_runtime.h>

// IntensityTransformation: out_k[b,c,h,w] = tf_k[b,c, round(255*img[b,c,h,w])]
// img: [B,C,H,W] f32 (B=8,C=3,H=W=1024), tf1/2/3: [B,C,256] f32.
// Output: concat(out1,out2,out3) -> 3*B*C*H*W floats.
//
// FINAL (verified over 11 rounds). This kernel is at the mixed-stream HBM3e
// roofline: 403 MB compulsory traffic (1:3 read:write) at the measured
// ~5.5 TB/s mixed ceiling = 62us kernel time, exactly as profiled
// (DRAM 69.7%, HBM 5.52 TB/s). Falsified alternatives: occupancy scaling
// (anti-correlated with DRAM%), conflict-free replicated LUT (neutral),
// store bursting (neutral), output-split CTAs (regressed), 512-thread CTAs
// (neutral), forced-occupancy regcap (regressed). L2->DRAM writeback order
// is hash-determined, so no SM-side issue reordering improves page locality.
//
// Config:
//  - TPB=256, ITER=4, grid (256,24), exact tiling: zero tail predicates
//  - loads-first prologue: 4 front-batched LDG.128 (MLP=4) issued before the
//    LUT fill so DRAM read latency hides fill + __syncthreads
//  - float4-packed 4KB shared LUT: one LDS.128 serves all 3 gathers/pixel
//  - __float2int_rn == jnp.round (round-half-even); idx in [0,255] by input
//    domain (uniform [0,1)), no clamp needed
//  - __ldcs loads / __stcs stores (single-touch streaming)
//  - 32-bit indexing throughout (max offset 18.9M < 2^31)

#define ITER 4
#define TPB  256

__global__ __launch_bounds__(TPB)
void intensity_lut_kernel(const float4* __restrict__ img,
                          const float*  __restrict__ tf1,
                          const float*  __restrict__ tf2,
                          const float*  __restrict__ tf3,
                          float4* __restrict__ out,
                          int hw4,     // H*W/4 per (b,c) plane (multiple of TPB*ITER)
                          int tot4)    // B*C*H*W/4 (stride between outputs)
{
    __shared__ float4 lut[256];

    const int bc = blockIdx.y;
    const int t  = threadIdx.x;

    const int base = bc * hw4 + blockIdx.x * (TPB * ITER) + t;
    const float4* __restrict__ src  = img + base;
    float4* __restrict__ dst0 = out + base;
    float4* __restrict__ dst1 = dst0 + tot4;
    float4* __restrict__ dst2 = dst1 + tot4;

    // Phase 1: front-batched img loads (MLP=4), independent of shared memory.
    // Their ~600-cycle DRAM latency fully hides the LUT fill + barrier.
    float4 v[ITER];
#pragma unroll
    for (int k = 0; k < ITER; k++)
        v[k] = __ldcs(&src[k * TPB]);

    // Phase 2: LUT fill (72KB of LUTs total -> L2-resident after first wave).
    if (t < 256) {
        const int g = bc * 256 + t;
        lut[t] = make_float4(tf1[g], tf2[g], tf3[g], 0.0f);
    }
    __syncthreads();

    // Phase 3: gather + store.
#pragma unroll
    for (int k = 0; k < ITER; k++) {
        // idx in [0,255] guaranteed (img uniform in [0,1)).
        const int i0 = __float2int_rn(255.0f * v[k].x);
        const int i1 = __float2int_rn(255.0f * v[k].y);
        const int i2 = __float2int_rn(255.0f * v[k].z);
        const int i3 = __float2int_rn(255.0f * v[k].w);

        const float4 l0 = lut[i0];
        const float4 l1 = lut[i1];
        const float4 l2 = lut[i2];
        const float4 l3 = lut[i3];

        __stcs(&dst0[k * TPB], make_float4(l0.x, l1.x, l2.x, l3.x));
        __stcs(&dst1[k * TPB], make_float4(l0.y, l1.y, l2.y, l3.y));
        __stcs(&dst2[k * TPB], make_float4(l0.z, l1.z, l2.z, l3.z));
    }
}

extern "C" void kernel_launch(void* const* d_in, const int* in_sizes, int n_in,
                              void* d_out, int out_size) {
    const float* img = (const float*)d_in[0];
    const float* tf1 = (const float*)d_in[1];
    const float* tf2 = (const float*)d_in[2];
    const float* tf3 = (const float*)d_in[3];
    float* out = (float*)d_out;

    const int n_img  = in_sizes[0];          // B*C*H*W
    const int n_lut  = in_sizes[1];          // B*C*256
    const int BC     = n_lut / 256;          // 24
    const int HW     = n_img / BC;           // 1048576
    const int hw4    = HW / 4;               // 262144 (= 256 * 1024 exactly)
    const int tot4   = n_img / 4;            // 6291456

    dim3 block(TPB);
    const int per_cta = TPB * ITER;          // 1024
    dim3 grid(hw4 / per_cta, BC);            // (256, 24) — exact, no tail
    intensity_lut_kernel<<<grid, block>>>(
        (const float4*)img, tf1, tf2, tf3, (float4*)out, hw4, tot4);
}